// round 1
// baseline (speedup 1.0000x reference)
#include <cuda_runtime.h>

// Problem shape (fixed by the dataset): image [8,512,512,16] f32, flow [8,512,512,2] f32
// output [8,512,512,16] f32.
constexpr int B = 8;
constexpr int H = 512;
constexpr int W = 512;
constexpr int C = 16;               // floats per pixel
constexpr int C4 = C / 4;           // float4 chunks per pixel = 4
constexpr int NPIX = B * H * W;     // 2,097,152
constexpr int N4 = NPIX * C4;       // 8,388,608 float4 outputs

__device__ __forceinline__ float4 lerp4(float4 a, float4 b, float t) {
    float4 r;
    r.x = fmaf(t, b.x - a.x, a.x);
    r.y = fmaf(t, b.y - a.y, a.y);
    r.z = fmaf(t, b.z - a.z, a.z);
    r.w = fmaf(t, b.w - a.w, a.w);
    return r;
}

__global__ __launch_bounds__(256)
void dense_image_warp_kernel(const float4* __restrict__ img,   // [B*H*W*C4] float4
                             const float2* __restrict__ flow,  // [B*H*W] float2 (dy,dx)
                             float4* __restrict__ out)         // [B*H*W*C4] float4
{
    int tid = blockIdx.x * blockDim.x + threadIdx.x;
    if (tid >= N4) return;

    int pix   = tid >> 2;       // pixel index
    int chunk = tid & 3;        // which float4 of the 16 channels

    int x = pix & (W - 1);
    int y = (pix >> 9) & (H - 1);
    int b = pix >> 18;

    float2 f = flow[pix];       // f.x = flow[...,0] (dy), f.y = flow[...,1] (dx)
    float qy = (float)y - f.x;
    float qx = (float)x - f.y;

    // tfa clamping semantics: floor clamped to [0, size-2], alpha clamped to [0,1]
    float fy = fminf(fmaxf(floorf(qy), 0.0f), (float)(H - 2));
    float fx = fminf(fmaxf(floorf(qx), 0.0f), (float)(W - 2));
    float ay = fminf(fmaxf(qy - fy, 0.0f), 1.0f);
    float ax = fminf(fmaxf(qx - fx, 0.0f), 1.0f);
    int iy = (int)fy;
    int ix = (int)fx;

    // float4 index of top-left corner's chunk
    int base = ((b * H + iy) * W + ix) * C4 + chunk;

    float4 tl = img[base];
    float4 tr = img[base + C4];           // ix+1
    float4 bl = img[base + W * C4];       // iy+1
    float4 br = img[base + W * C4 + C4];  // iy+1, ix+1

    float4 top = lerp4(tl, tr, ax);
    float4 bot = lerp4(bl, br, ax);
    float4 res = lerp4(top, bot, ay);

    out[tid] = res;
}

extern "C" void kernel_launch(void* const* d_in, const int* in_sizes, int n_in,
                              void* d_out, int out_size) {
    const float4* img  = (const float4*)d_in[0];
    const float2* flow = (const float2*)d_in[1];
    float4* out = (float4*)d_out;

    int threads = 256;
    int blocks = (N4 + threads - 1) / threads;
    dense_image_warp_kernel<<<blocks, threads>>>(img, flow, out);
}